// round 6
// baseline (speedup 1.0000x reference)
#include <cuda_runtime.h>
#include <cuda_bf16.h>

// SSIM loss, fully fused single kernel. (1,3,2048,2048) fp32, VALID 11-tap
// separable Gaussian (sigma=1.5). out = 1 - mean(ssim_map) over (3,2038,2038).
//
// v6 = exact v2 compute (proven fastest geometry: 32x32 tile, 128 thr,
// strides 43/33, FFMA-imm convs) + deterministic fixed-point reduction folded
// into the main kernel via last-block-done (no tail kernels at all).

#define H_DIM 2048
#define W_DIM 2048
#define OUT_DIM 2038
#define TILE 32
#define IN_TILE 42
#define NTHREADS 128
#define GRID_X 64
#define GRID_Y 64
#define NBLOCKS (GRID_X * GRID_Y * 3)

// Normalized gaussian(sigma=1.5, size=11); sum == 1.0f.
#define W0 0.00102841f
#define W1 0.00759878f
#define W2 0.03600077f
#define W3 0.10936067f
#define W4 0.21300553f
#define W5 0.26601168f

#define FIXED_SCALE 16777216.0   // 2^24

__device__ unsigned long long g_accum = 0ull;
__device__ unsigned int g_done = 0u;

// 8 x 11-tap dot products over an 18-wide window; constant weights -> FFMA-imm.
__device__ __forceinline__ void conv11(const float* __restrict__ v,
                                       float* __restrict__ acc) {
    const float W[11] = {W0, W1, W2, W3, W4, W5, W4, W3, W2, W1, W0};
    #pragma unroll
    for (int j = 0; j < 8; ++j) {
        float a = W0 * v[j];
        #pragma unroll
        for (int t = 1; t < 11; ++t)
            a = fmaf(W[t], v[j + t], a);
        acc[j] = a;
    }
}

__global__ __launch_bounds__(NTHREADS)
void ssim_main_kernel(const float* __restrict__ xin, const float* __restrict__ yin,
                      float* __restrict__ out) {
    __shared__ float sx[IN_TILE][43];    // conflict-free window loads
    __shared__ float sy[IN_TILE][43];
    __shared__ float hb[5][IN_TILE][33]; // conflict-free stores + vertical reads
    __shared__ float red[4];

    const int tid = threadIdx.x;
    const int gx0 = blockIdx.x * TILE;
    const int gy0 = blockIdx.y * TILE;
    const float* __restrict__ xp = xin + (size_t)blockIdx.z * (H_DIM * W_DIM);
    const float* __restrict__ yp = yin + (size_t)blockIdx.z * (H_DIM * W_DIM);

    // ---- Load 42x42 x,y tile ----
    if (gx0 + IN_TILE <= W_DIM && gy0 + IN_TILE <= H_DIM) {
        // interior fast path: no bounds predicates
        #pragma unroll 1
        for (int i = tid; i < IN_TILE * IN_TILE; i += NTHREADS) {
            int r = i / IN_TILE;
            int c = i - r * IN_TILE;
            int idx = (gy0 + r) * W_DIM + gx0 + c;
            sx[r][c] = __ldg(xp + idx);
            sy[r][c] = __ldg(yp + idx);
        }
    } else {
        #pragma unroll 1
        for (int i = tid; i < IN_TILE * IN_TILE; i += NTHREADS) {
            int r = i / IN_TILE;
            int c = i - r * IN_TILE;
            int gr = gy0 + r;
            int gc = gx0 + c;
            float xv = 0.0f, yv = 0.0f;
            if (gr < H_DIM && gc < W_DIM) {
                int idx = gr * W_DIM + gc;
                xv = __ldg(xp + idx);
                yv = __ldg(yp + idx);
            }
            sx[r][c] = xv;
            sy[r][c] = yv;
        }
    }
    __syncthreads();

    // ---- Phase A: horizontal blur of 5 maps; 42 rows x 4 runs of 8 ----
    for (int task = tid; task < IN_TILE * 4; task += NTHREADS) {
        int r  = task >> 2;
        int c0 = (task & 3) << 3;
        float xw[18], yw[18], pw[18], acc[8];

        #pragma unroll
        for (int k = 0; k < 18; ++k) xw[k] = sx[r][c0 + k];
        conv11(xw, acc);
        #pragma unroll
        for (int j = 0; j < 8; ++j) hb[0][r][c0 + j] = acc[j];

        #pragma unroll
        for (int k = 0; k < 18; ++k) yw[k] = sy[r][c0 + k];
        conv11(yw, acc);
        #pragma unroll
        for (int j = 0; j < 8; ++j) hb[1][r][c0 + j] = acc[j];

        #pragma unroll
        for (int k = 0; k < 18; ++k) pw[k] = xw[k] * xw[k];
        conv11(pw, acc);
        #pragma unroll
        for (int j = 0; j < 8; ++j) hb[2][r][c0 + j] = acc[j];

        #pragma unroll
        for (int k = 0; k < 18; ++k) pw[k] = yw[k] * yw[k];
        conv11(pw, acc);
        #pragma unroll
        for (int j = 0; j < 8; ++j) hb[3][r][c0 + j] = acc[j];

        #pragma unroll
        for (int k = 0; k < 18; ++k) pw[k] = xw[k] * yw[k];
        conv11(pw, acc);
        #pragma unroll
        for (int j = 0; j < 8; ++j) hb[4][r][c0 + j] = acc[j];
    }
    __syncthreads();

    // ---- Phase B: vertical blur (8 rows/thread, 4 warps) + SSIM + reduce ----
    const int tx  = tid & 31;
    const int tg  = tid >> 5;
    const int oyb = tg << 3;

    float acc[5][8];
    #pragma unroll
    for (int m = 0; m < 5; ++m) {
        float v[18];
        #pragma unroll
        for (int k = 0; k < 18; ++k) v[k] = hb[m][oyb + k][tx];
        conv11(v, acc[m]);
    }

    const float C1 = 0.01f * 0.01f;
    const float C2 = 0.03f * 0.03f;
    float lsum = 0.0f;
    const int ox = gx0 + tx;
    #pragma unroll
    for (int j = 0; j < 8; ++j) {
        int oy = gy0 + oyb + j;
        if (oy < OUT_DIM && ox < OUT_DIM) {
            float mu1 = acc[0][j], mu2 = acc[1][j];
            float m11 = mu1 * mu1;
            float m22 = mu2 * mu2;
            float m12 = mu1 * mu2;
            float s1  = acc[2][j] - m11;
            float s2  = acc[3][j] - m22;
            float s12 = acc[4][j] - m12;
            float num = (2.0f * m12 + C1) * (2.0f * s12 + C2);
            float den = (m11 + m22 + C1) * (s1 + s2 + C2);
            lsum += __fdividef(num, den);
        }
    }

    #pragma unroll
    for (int off = 16; off > 0; off >>= 1)
        lsum += __shfl_down_sync(0xffffffffu, lsum, off);
    if (tx == 0) red[tg] = lsum;
    __syncthreads();

    if (tid == 0) {
        float bs = red[0] + red[1] + red[2] + red[3];
        // Fixed-point accumulation: integer adds commute -> replay-deterministic.
        unsigned long long q =
            (unsigned long long)__double2ll_rn((double)bs * FIXED_SCALE);
        atomicAdd(&g_accum, q);
        __threadfence();
        unsigned int ticket = atomicAdd(&g_done, 1u);
        if (ticket == NBLOCKS - 1) {
            // Last block: finalize and reset for the next graph replay.
            unsigned long long total = g_accum;
            double mean = ((double)total / FIXED_SCALE) /
                          (3.0 * (double)OUT_DIM * (double)OUT_DIM);
            out[0] = 1.0f - (float)mean;
            g_accum = 0ull;
            g_done = 0u;
        }
    }
}

extern "C" void kernel_launch(void* const* d_in, const int* in_sizes, int n_in,
                              void* d_out, int out_size) {
    const float* pred = (const float*)d_in[0];
    const float* targ = (const float*)d_in[1];
    float* out = (float*)d_out;

    dim3 grid(GRID_X, GRID_Y, 3);
    ssim_main_kernel<<<grid, NTHREADS>>>(pred, targ, out);
}

// round 7
// speedup vs baseline: 1.0280x; 1.0280x over previous
#include <cuda_runtime.h>
#include <cuda_bf16.h>

// SSIM loss, fully fused. (1,3,2048,2048) fp32, VALID 11-tap separable Gaussian
// (sigma=1.5). Output scalar fp32 = 1 - mean(ssim_map) over (3,2038,2038).
//
// v7 = exact v2 main kernel (proven ~104us: 32x32 tile, 128 thr, strides 43/33,
// FFMA-imm convs, compiler-unrolled tile load) + deterministic fixed-point
// ull atomic reduction with a 1-thread finalize kernel (~4us tail, proven).

#define H_DIM 2048
#define W_DIM 2048
#define OUT_DIM 2038
#define TILE 32
#define IN_TILE 42
#define NTHREADS 128
#define GRID_X 64
#define GRID_Y 64

// Normalized gaussian(sigma=1.5, size=11); sum == 1.0f.
#define W0 0.00102841f
#define W1 0.00759878f
#define W2 0.03600077f
#define W3 0.10936067f
#define W4 0.21300553f
#define W5 0.26601168f

#define FIXED_SCALE 16777216.0   // 2^24

__device__ unsigned long long g_accum = 0ull;

// 8 x 11-tap dot products over an 18-wide window; constant weights -> FFMA-imm.
__device__ __forceinline__ void conv11(const float* __restrict__ v,
                                       float* __restrict__ acc) {
    const float W[11] = {W0, W1, W2, W3, W4, W5, W4, W3, W2, W1, W0};
    #pragma unroll
    for (int j = 0; j < 8; ++j) {
        float a = W0 * v[j];
        #pragma unroll
        for (int t = 1; t < 11; ++t)
            a = fmaf(W[t], v[j + t], a);
        acc[j] = a;
    }
}

__global__ __launch_bounds__(NTHREADS)
void ssim_main_kernel(const float* __restrict__ xin, const float* __restrict__ yin) {
    __shared__ float sx[IN_TILE][43];    // conflict-free window loads
    __shared__ float sy[IN_TILE][43];
    __shared__ float hb[5][IN_TILE][33]; // conflict-free stores + vertical reads
    __shared__ float red[4];

    const int tid = threadIdx.x;
    const int gx0 = blockIdx.x * TILE;
    const int gy0 = blockIdx.y * TILE;
    const float* __restrict__ xp = xin + (size_t)blockIdx.z * (H_DIM * W_DIM);
    const float* __restrict__ yp = yin + (size_t)blockIdx.z * (H_DIM * W_DIM);

    // ---- Load 42x42 x,y tile (zero clamp at image edge); compiler-unrolled
    // so LDGs batch for high MLP ----
    for (int i = tid; i < IN_TILE * IN_TILE; i += NTHREADS) {
        int r = i / IN_TILE;
        int c = i - r * IN_TILE;
        int gr = gy0 + r;
        int gc = gx0 + c;
        float xv = 0.0f, yv = 0.0f;
        if (gr < H_DIM && gc < W_DIM) {
            int idx = gr * W_DIM + gc;
            xv = __ldg(xp + idx);
            yv = __ldg(yp + idx);
        }
        sx[r][c] = xv;
        sy[r][c] = yv;
    }
    __syncthreads();

    // ---- Phase A: horizontal blur of 5 maps; 42 rows x 4 runs of 8 ----
    for (int task = tid; task < IN_TILE * 4; task += NTHREADS) {
        int r  = task >> 2;
        int c0 = (task & 3) << 3;
        float xw[18], yw[18], pw[18], acc[8];

        #pragma unroll
        for (int k = 0; k < 18; ++k) xw[k] = sx[r][c0 + k];
        conv11(xw, acc);
        #pragma unroll
        for (int j = 0; j < 8; ++j) hb[0][r][c0 + j] = acc[j];

        #pragma unroll
        for (int k = 0; k < 18; ++k) yw[k] = sy[r][c0 + k];
        conv11(yw, acc);
        #pragma unroll
        for (int j = 0; j < 8; ++j) hb[1][r][c0 + j] = acc[j];

        #pragma unroll
        for (int k = 0; k < 18; ++k) pw[k] = xw[k] * xw[k];
        conv11(pw, acc);
        #pragma unroll
        for (int j = 0; j < 8; ++j) hb[2][r][c0 + j] = acc[j];

        #pragma unroll
        for (int k = 0; k < 18; ++k) pw[k] = yw[k] * yw[k];
        conv11(pw, acc);
        #pragma unroll
        for (int j = 0; j < 8; ++j) hb[3][r][c0 + j] = acc[j];

        #pragma unroll
        for (int k = 0; k < 18; ++k) pw[k] = xw[k] * yw[k];
        conv11(pw, acc);
        #pragma unroll
        for (int j = 0; j < 8; ++j) hb[4][r][c0 + j] = acc[j];
    }
    __syncthreads();

    // ---- Phase B: vertical blur (8 rows/thread, 4 warps) + SSIM + reduce ----
    const int tx  = tid & 31;
    const int tg  = tid >> 5;
    const int oyb = tg << 3;

    float acc[5][8];
    #pragma unroll
    for (int m = 0; m < 5; ++m) {
        float v[18];
        #pragma unroll
        for (int k = 0; k < 18; ++k) v[k] = hb[m][oyb + k][tx];
        conv11(v, acc[m]);
    }

    const float C1 = 0.01f * 0.01f;
    const float C2 = 0.03f * 0.03f;
    float lsum = 0.0f;
    const int ox = gx0 + tx;
    #pragma unroll
    for (int j = 0; j < 8; ++j) {
        int oy = gy0 + oyb + j;
        if (oy < OUT_DIM && ox < OUT_DIM) {
            float mu1 = acc[0][j], mu2 = acc[1][j];
            float m11 = mu1 * mu1;
            float m22 = mu2 * mu2;
            float m12 = mu1 * mu2;
            float s1  = acc[2][j] - m11;
            float s2  = acc[3][j] - m22;
            float s12 = acc[4][j] - m12;
            float num = (2.0f * m12 + C1) * (2.0f * s12 + C2);
            float den = (m11 + m22 + C1) * (s1 + s2 + C2);
            lsum += __fdividef(num, den);
        }
    }

    #pragma unroll
    for (int off = 16; off > 0; off >>= 1)
        lsum += __shfl_down_sync(0xffffffffu, lsum, off);
    if (tx == 0) red[tg] = lsum;
    __syncthreads();
    if (tid == 0) {
        float bs = red[0] + red[1] + red[2] + red[3];
        // Fixed-point: integer adds commute -> replay-deterministic.
        unsigned long long q =
            (unsigned long long)__double2ll_rn((double)bs * FIXED_SCALE);
        atomicAdd(&g_accum, q);
    }
}

__global__ void ssim_final_kernel(float* __restrict__ out) {
    unsigned long long v = g_accum;
    g_accum = 0ull;   // reset for next graph replay
    double mean = ((double)v / FIXED_SCALE) / (3.0 * (double)OUT_DIM * (double)OUT_DIM);
    out[0] = 1.0f - (float)mean;
}

extern "C" void kernel_launch(void* const* d_in, const int* in_sizes, int n_in,
                              void* d_out, int out_size) {
    const float* pred = (const float*)d_in[0];
    const float* targ = (const float*)d_in[1];
    float* out = (float*)d_out;

    dim3 grid(GRID_X, GRID_Y, 3);
    ssim_main_kernel<<<grid, NTHREADS>>>(pred, targ);
    ssim_final_kernel<<<1, 1>>>(out);
}